// round 13
// baseline (speedup 1.0000x reference)
#include <cuda_runtime.h>
#include <cuda_fp16.h>
#include <cstdint>
#include <cstddef>

#define BATCH 4
#define CHAN  128
#define HH    96
#define WW    96
#define MD    20
#define KD    41
#define OHH   48
#define OWW   48

// fp16 channel-last staging: x[b][h][w][ch]
__device__ __half x1t_g[BATCH * HH * WW * CHAN];
__device__ __half x2t_g[BATCH * HH * WW * CHAN];

// ---------- prepass: fp32 [b][ch][h][w] -> fp16 [b][h][w][ch] ----------
__global__ void __launch_bounds__(256, 4)
cvt_kernel(const float* __restrict__ x1, const float* __restrict__ x2)
{
    __shared__ __half2 hsm[WW * 65];
    const int h = blockIdx.x, b = blockIdx.y;
    const float* src = (blockIdx.z == 0) ? x1 : x2;
    __half* dst = (blockIdx.z == 0) ? x1t_g : x2t_g;
    const float* sp = src + ((size_t)b * CHAN) * (HH * WW) + (size_t)h * WW;

    const int cp0 = threadIdx.x >> 3;
    const int wq8 = threadIdx.x & 7;
#pragma unroll
    for (int cph = 0; cph < 2; ++cph) {
        int cp = cp0 + 32 * cph;
        const float* r0 = sp + (size_t)(2 * cp) * (HH * WW);
        const float* r1 = r0 + HH * WW;
#pragma unroll
        for (int it = 0; it < 3; ++it) {
            int wq = wq8 + 8 * it;
            float4 a = *reinterpret_cast<const float4*>(r0 + 4 * wq);
            float4 c = *reinterpret_cast<const float4*>(r1 + 4 * wq);
            hsm[(4 * wq + 0) * 65 + cp] = __floats2half2_rn(a.x, c.x);
            hsm[(4 * wq + 1) * 65 + cp] = __floats2half2_rn(a.y, c.y);
            hsm[(4 * wq + 2) * 65 + cp] = __floats2half2_rn(a.z, c.z);
            hsm[(4 * wq + 3) * 65 + cp] = __floats2half2_rn(a.w, c.w);
        }
    }
    __syncthreads();
    __half2* dp = reinterpret_cast<__half2*>(dst + ((size_t)(b * HH + h)) * WW * CHAN);
    for (int idx = threadIdx.x; idx < WW * (CHAN / 2); idx += 256) {
        int w = idx >> 6, cp = idx & 63;
        dp[w * (CHAN / 2) + cp] = hsm[w * 65 + cp];
    }
}

// ---------- main kernel ----------
#define NT     384
#define SLAB   24576                     // 96 rows x 256B
#define SA0    0
#define SA1    SLAB
#define SB     (2 * SLAB)                // 3-slot B ring
#define SCB    (5 * SLAB)
#define CBST   68                        // permuted Cbuf row stride (words)
#define CBPL   (16 * CBST * 4)           // 4352 B per plane
#define CBUF   (6 * CBPL)                // 26112 B per C buffer
#define SMEM_MAIN (SCB + 2 * CBUF)       // 175104 B

__device__ __forceinline__ uint32_t smem_u32(const void* p) {
    uint32_t a;
    asm("{ .reg .u64 t; cvta.to.shared.u64 t, %1; cvt.u32.u64 %0, t; }" : "=r"(a) : "l"(p));
    return a;
}
__device__ __forceinline__ void cpa16(uint32_t dst, const void* src, uint32_t sz) {
    asm volatile("cp.async.ca.shared.global [%0], [%1], 16, %2;"
                 :: "r"(dst), "l"(src), "r"(sz) : "memory");
}
__device__ __forceinline__ void fill_slab(uint32_t dstb, const __half* src,
                                          bool valid, int tid)
{
#pragma unroll
    for (int it = 0; it < 4; ++it) {
        int q = tid + it * NT;
        int n = q >> 4, c = q & 15;
        uint32_t dst = dstb + n * 256 + ((c ^ (n & 7)) << 4);
        cpa16(dst, src + n * CHAN + c * 8, valid ? 16u : 0u);
    }
}
__device__ __forceinline__ void ldsm4(uint32_t& r0, uint32_t& r1, uint32_t& r2,
                                      uint32_t& r3, uint32_t a) {
    asm volatile("ldmatrix.sync.aligned.m8n8.x4.shared.b16 {%0,%1,%2,%3}, [%4];"
                 : "=r"(r0), "=r"(r1), "=r"(r2), "=r"(r3) : "r"(a));
}
__device__ __forceinline__ void mma16816(float* c, const uint32_t* a,
                                         uint32_t b0, uint32_t b1) {
    asm volatile("mma.sync.aligned.m16n8k16.row.col.f32.f16.f16.f32 "
                 "{%0,%1,%2,%3},{%4,%5,%6,%7},{%8,%9},{%0,%1,%2,%3};"
                 : "+f"(c[0]), "+f"(c[1]), "+f"(c[2]), "+f"(c[3])
                 : "r"(a[0]), "r"(a[1]), "r"(a[2]), "r"(a[3]), "r"(b0), "r"(b1));
}

// software-pipelined across ks: ldsm(ks+1) issues before the 16 MMAs of ks
template <bool DOP, bool DOC>
__device__ __forceinline__ void mma_row(uint32_t bb, uint32_t boff0, uint32_t boff1,
                                        int swb0, int swb1, int bhi,
                                        const uint32_t aR[2][8][4],
                                        float accP[4][4], float accC[4][4])
{
    uint32_t bf[2][4], cf[2][4];
    ldsm4(bf[0][0], bf[0][1], bf[0][2], bf[0][3],
          bb + boff0 + (((bhi) ^ swb0) << 4));
    ldsm4(cf[0][0], cf[0][1], cf[0][2], cf[0][3],
          bb + boff1 + (((bhi) ^ swb1) << 4));
#pragma unroll
    for (int ks = 0; ks < 8; ++ks) {
        const int cur = ks & 1, nxt = cur ^ 1;
        if (ks < 7) {
            ldsm4(bf[nxt][0], bf[nxt][1], bf[nxt][2], bf[nxt][3],
                  bb + boff0 + (((2 * (ks + 1) + bhi) ^ swb0) << 4));
            ldsm4(cf[nxt][0], cf[nxt][1], cf[nxt][2], cf[nxt][3],
                  bb + boff1 + (((2 * (ks + 1) + bhi) ^ swb1) << 4));
        }
        if (DOP) { mma16816(accP[0], aR[1][ks], bf[cur][0], bf[cur][1]);
                   mma16816(accP[1], aR[1][ks], bf[cur][2], bf[cur][3]);
                   mma16816(accP[2], aR[1][ks], cf[cur][0], cf[cur][1]);
                   mma16816(accP[3], aR[1][ks], cf[cur][2], cf[cur][3]); }
        if (DOC) { mma16816(accC[0], aR[0][ks], bf[cur][0], bf[cur][1]);
                   mma16816(accC[1], aR[0][ks], bf[cur][2], bf[cur][3]);
                   mma16816(accC[2], aR[0][ks], cf[cur][0], cf[cur][1]);
                   mma16816(accC[3], aR[0][ks], cf[cur][2], cf[cur][3]); }
    }
}

// banded gather -> out; __noinline__ so its ~10 addressing constants are NOT
// live across the mainloop (frees registers for the ldsm pipeline)
__device__ __noinline__ void gather_out(float* __restrict__ outg, const char* smc,
                                        int jg, int buf, int oh, int b)
{
    const int tid = threadIdx.x;
    const int owg = tid % 48;
    const int i0g = tid / 48;
    const int m2  = owg >> 3;
    const int cs2 = min(max(16 * m2 - 24, 0), 32);
    const int r0g = (2 * owg) & 15;
    const int c2b = 2 * owg + i0g - MD;
    const int par = c2b & 1;
    const int base0 = m2 * (CBPL / 4) + r0g * CBST;
    const int base1 = base0 + CBST;
    const float* CB = reinterpret_cast<const float*>(smc + SCB + buf * CBUF);
    const float* zp = CB + 32;
    float* op = outg + ((size_t)b * (KD * KD) + (size_t)i0g * KD + jg) * (OHH * OWW)
                + (size_t)oh * OWW + owg;
#pragma unroll
    for (int s = 0; s < 6; ++s) {
        if (s == 5 && tid >= 48) break;
        int c2 = c2b + 8 * s;
        int cl0 = c2 - cs2;
        int cl1 = cl0 + 1;
        const float* p0 = ((unsigned)c2 < 96u)
            ? (CB + base0 + (cl0 >> 1) + par * 33) : zp;
        const float* p1 = ((unsigned)(c2 + 1) < 96u)
            ? (CB + base1 + (cl1 >> 1) + (1 - par) * 33) : zp;
        op[(size_t)s * (8 * KD * OHH * OWW)] = (*p0 + *p1) * (1.0f / 512.0f);
    }
}

__global__ void __launch_bounds__(NT, 1)
corr_hmma_kernel(float* __restrict__ outg)
{
    extern __shared__ char smc[];
    const uint32_t sb = smem_u32(smc);
    const int tid = threadIdx.x, warp = tid >> 5, lane = tid & 31;
    const int m = warp >> 1;
    const int nh = warp & 1;
    const int jb = blockIdx.x, oh = blockIdx.y, b = blockIdx.z;
    const int j0 = jb * 14;
    const int cnt = (jb == 2) ? 13 : 14;   // rows used: R0 .. R0+cnt
    const int R0 = 2 * oh + j0 - MD;

    // ---- prolog fills: group A = {A0,A1}, group B0 = {rows R0,R0+1} ----
    const __half* x1b = x1t_g + ((size_t)(b * HH + 2 * oh)) * WW * CHAN;
    fill_slab(sb + SA0, x1b, true, tid);
    fill_slab(sb + SA1, x1b + WW * CHAN, true, tid);
    asm volatile("cp.async.commit_group;" ::: "memory");     // GA
    const __half* x2bb = x2t_g + (size_t)b * HH * WW * CHAN;
#pragma unroll
    for (int k = 0; k < 2; ++k) {
        int row = R0 + k;
        bool v = (unsigned)row < HH;
        fill_slab(sb + SB + k * SLAB, x2bb + (size_t)(v ? row : 0) * WW * CHAN, v, tid);
    }
    asm volatile("cp.async.commit_group;" ::: "memory");     // GB0

    // ---- ldmatrix addressing ----
    const int cs = min(max(16 * m - 24, 0), 32);
    const int ra = m * 16 + (lane & 15);
    const uint32_t aoff = (uint32_t)(ra * 256);
    const int swa = ra & 7;
    const int ahi = lane >> 4;
    int rb0 = cs + (nh * 4 + 0 + (lane >> 4)) * 8 + (lane & 7);
    int rb1 = cs + (nh * 4 + 2 + (lane >> 4)) * 8 + (lane & 7);
    const uint32_t boff0 = (uint32_t)(rb0 * 256);
    const uint32_t boff1 = (uint32_t)(rb1 * 256);
    const int swb0 = rb0 & 7, swb1 = rb1 & 7;
    const int bhi = (lane >> 3) & 1;

    // zero pad slot (col 32 of every plane-row, both buffers)
    {
        int plane = tid >> 5, rem = tid & 31;
        float* P = reinterpret_cast<float*>(smc + SCB + plane * CBPL);
        if (rem < 16) P[rem * CBST + 32] = 0.f;
        else P[(rem - 16) * CBST + 66] = 0.f;
    }

    // ---- hoist A fragments (A group done; B group may still be in flight) ----
    asm volatile("cp.async.wait_group 1;" ::: "memory");
    __syncthreads();
    uint32_t aR[2][8][4];
#pragma unroll
    for (int h = 0; h < 2; ++h) {
        const uint32_t ab = sb + (h ? SA1 : SA0) + aoff;
#pragma unroll
        for (int ks = 0; ks < 8; ++ks)
            ldsm4(aR[h][ks][0], aR[h][ks][1], aR[h][ks][2], aR[h][ks][3],
                  ab + (((2 * ks + ahi) ^ swa) << 4));
    }

    const int spOffW = m * (CBPL / 4);
    const int gr = lane >> 2, kk = lane & 3;

    float accP[4][4], accC[4][4];
#pragma unroll
    for (int t = 0; t < 4; ++t)
#pragma unroll
        for (int q = 0; q < 4; ++q) { accP[t][q] = 0.f; accC[t][q] = 0.f; }

    // loop: iter l consumes B row R0+l once.  Protocol (race-free):
    //   wait_group (row l complete, this thread) -> __syncthreads (publish all)
    //   -> prefetch row l+2 -> gather(l-2) -> mma(row l) -> spill(l-1)
    for (int l = 0; l <= cnt; ++l) {
        if (l == 0) asm volatile("cp.async.wait_group 0;" ::: "memory");
        else        asm volatile("cp.async.wait_group 1;" ::: "memory");
        __syncthreads();

        if (l + 2 <= cnt) {
            int row = R0 + l + 2;
            bool v = (unsigned)row < HH;
            fill_slab(sb + SB + ((l + 2) % 3) * SLAB,
                      x2bb + (size_t)(v ? row : 0) * WW * CHAN, v, tid);
        }
        asm volatile("cp.async.commit_group;" ::: "memory");

        if (l >= 2) gather_out(outg, smc, j0 + l - 2, (l + 1) & 1, oh, b);

        const uint32_t bb = sb + SB + (uint32_t)((l % 3) * SLAB);
        if (l == 0)
            mma_row<false, true >(bb, boff0, boff1, swb0, swb1, bhi, aR, accP, accC);
        else if (l == cnt)
            mma_row<true , false>(bb, boff0, boff1, swb0, swb1, bhi, aR, accP, accC);
        else
            mma_row<true , true >(bb, boff0, boff1, swb0, swb1, bhi, aR, accP, accC);

        // spill accP = GEMM(j0+l-1) into buffer l&1 (permuted layout)
        if (l >= 1) {
            float* Cbm = reinterpret_cast<float*>(smc + SCB + (l & 1) * CBUF) + spOffW;
#pragma unroll
            for (int t = 0; t < 4; ++t) {
                int n = nh * 4 + t;
                int slot = n * 4 + kk;
                Cbm[gr * CBST + slot]            = accP[t][0];
                Cbm[gr * CBST + slot + 33]       = accP[t][1];
                Cbm[(gr + 8) * CBST + slot]      = accP[t][2];
                Cbm[(gr + 8) * CBST + slot + 33] = accP[t][3];
            }
        }
#pragma unroll
        for (int t = 0; t < 4; ++t)
#pragma unroll
            for (int q = 0; q < 4; ++q) { accP[t][q] = accC[t][q]; accC[t][q] = 0.f; }
    }
    __syncthreads();
    gather_out(outg, smc, j0 + cnt - 1, cnt & 1, oh, b);
}

extern "C" void kernel_launch(void* const* d_in, const int* in_sizes, int n_in,
                              void* d_out, int out_size)
{
    (void)in_sizes; (void)n_in; (void)out_size;
    const float* x1 = (const float*)d_in[0];
    const float* x2 = (const float*)d_in[1];
    float* out = (float*)d_out;

    static bool attr_set = false;
    if (!attr_set) {
        cudaFuncSetAttribute(corr_hmma_kernel, cudaFuncAttributeMaxDynamicSharedMemorySize,
                             SMEM_MAIN);
        attr_set = true;
    }
    cvt_kernel<<<dim3(HH, BATCH, 2), 256>>>(x1, x2);
    corr_hmma_kernel<<<dim3(3, OHH, BATCH), NT, SMEM_MAIN>>>(out);
}

// round 14
// speedup vs baseline: 1.1037x; 1.1037x over previous
#include <cuda_runtime.h>
#include <cuda_fp16.h>
#include <cstdint>
#include <cstddef>

#define BATCH 4
#define CHAN  128
#define HH    96
#define WW    96
#define MD    20
#define KD    41
#define OHH   48
#define OWW   48

// fp16 channel-last staging: x[b][h][w][ch]
__device__ __half x1t_g[BATCH * HH * WW * CHAN];
__device__ __half x2t_g[BATCH * HH * WW * CHAN];

// ---------- prepass: fp32 [b][ch][h][w] -> fp16 [b][h][w][ch] ----------
__global__ void __launch_bounds__(256, 4)
cvt_kernel(const float* __restrict__ x1, const float* __restrict__ x2)
{
    __shared__ __half2 hsm[WW * 65];
    const int h = blockIdx.x, b = blockIdx.y;
    const float* src = (blockIdx.z == 0) ? x1 : x2;
    __half* dst = (blockIdx.z == 0) ? x1t_g : x2t_g;
    const float* sp = src + ((size_t)b * CHAN) * (HH * WW) + (size_t)h * WW;

    const int cp0 = threadIdx.x >> 3;
    const int wq8 = threadIdx.x & 7;
#pragma unroll
    for (int cph = 0; cph < 2; ++cph) {
        int cp = cp0 + 32 * cph;
        const float* r0 = sp + (size_t)(2 * cp) * (HH * WW);
        const float* r1 = r0 + HH * WW;
#pragma unroll
        for (int it = 0; it < 3; ++it) {
            int wq = wq8 + 8 * it;
            float4 a = *reinterpret_cast<const float4*>(r0 + 4 * wq);
            float4 c = *reinterpret_cast<const float4*>(r1 + 4 * wq);
            hsm[(4 * wq + 0) * 65 + cp] = __floats2half2_rn(a.x, c.x);
            hsm[(4 * wq + 1) * 65 + cp] = __floats2half2_rn(a.y, c.y);
            hsm[(4 * wq + 2) * 65 + cp] = __floats2half2_rn(a.z, c.z);
            hsm[(4 * wq + 3) * 65 + cp] = __floats2half2_rn(a.w, c.w);
        }
    }
    __syncthreads();
    __half2* dp = reinterpret_cast<__half2*>(dst + ((size_t)(b * HH + h)) * WW * CHAN);
    for (int idx = threadIdx.x; idx < WW * (CHAN / 2); idx += 256) {
        int w = idx >> 6, cp = idx & 63;
        dp[w * (CHAN / 2) + cp] = hsm[w * 65 + cp];
    }
}

// ---------- main kernel ----------
#define NT     384
#define SLAB   24576                     // 96 rows x 256B
#define SA0    0
#define SA1    SLAB
#define SB     (2 * SLAB)                // 3-slot B ring
#define SCB    (5 * SLAB)
#define CBST   68                        // permuted Cbuf row stride (words)
#define CBPL   (16 * CBST * 4)           // 4352 B per plane
#define CBUF   (6 * CBPL)                // 26112 B per C buffer
#define SMEM_MAIN (SCB + 2 * CBUF)       // 175104 B

__device__ __forceinline__ uint32_t smem_u32(const void* p) {
    uint32_t a;
    asm("{ .reg .u64 t; cvta.to.shared.u64 t, %1; cvt.u32.u64 %0, t; }" : "=r"(a) : "l"(p));
    return a;
}
__device__ __forceinline__ void cpa16(uint32_t dst, const void* src, uint32_t sz) {
    asm volatile("cp.async.ca.shared.global [%0], [%1], 16, %2;"
                 :: "r"(dst), "l"(src), "r"(sz) : "memory");
}
__device__ __forceinline__ void fill_slab(uint32_t dstb, const __half* src,
                                          bool valid, int tid)
{
#pragma unroll
    for (int it = 0; it < 4; ++it) {
        int q = tid + it * NT;
        int n = q >> 4, c = q & 15;
        uint32_t dst = dstb + n * 256 + ((c ^ (n & 7)) << 4);
        cpa16(dst, src + n * CHAN + c * 8, valid ? 16u : 0u);
    }
}
__device__ __forceinline__ void ldsm4(uint32_t& r0, uint32_t& r1, uint32_t& r2,
                                      uint32_t& r3, uint32_t a) {
    asm volatile("ldmatrix.sync.aligned.m8n8.x4.shared.b16 {%0,%1,%2,%3}, [%4];"
                 : "=r"(r0), "=r"(r1), "=r"(r2), "=r"(r3) : "r"(a));
}
__device__ __forceinline__ void mma16816(float* c, const uint32_t* a,
                                         uint32_t b0, uint32_t b1) {
    asm volatile("mma.sync.aligned.m16n8k16.row.col.f32.f16.f16.f32 "
                 "{%0,%1,%2,%3},{%4,%5,%6,%7},{%8,%9},{%0,%1,%2,%3};"
                 : "+f"(c[0]), "+f"(c[1]), "+f"(c[2]), "+f"(c[3])
                 : "r"(a[0]), "r"(a[1]), "r"(a[2]), "r"(a[3]), "r"(b0), "r"(b1));
}

template <bool DOP, bool DOC>
__device__ __forceinline__ void mma_row(uint32_t bb, uint32_t boff0, uint32_t boff1,
                                        int swb0, int swb1, int bhi,
                                        const uint32_t aR[2][8][4],
                                        float accP[4][4], float accC[4][4])
{
#pragma unroll
    for (int ks = 0; ks < 8; ++ks) {
        uint32_t b0, b1, b2, b3, c0, c1, c2, c3;
        ldsm4(b0, b1, b2, b3, bb + boff0 + (((2 * ks + bhi) ^ swb0) << 4));
        ldsm4(c0, c1, c2, c3, bb + boff1 + (((2 * ks + bhi) ^ swb1) << 4));
        if (DOP) { mma16816(accP[0], aR[1][ks], b0, b1);
                   mma16816(accP[1], aR[1][ks], b2, b3);
                   mma16816(accP[2], aR[1][ks], c0, c1);
                   mma16816(accP[3], aR[1][ks], c2, c3); }
        if (DOC) { mma16816(accC[0], aR[0][ks], b0, b1);
                   mma16816(accC[1], aR[0][ks], b2, b3);
                   mma16816(accC[2], aR[0][ks], c0, c1);
                   mma16816(accC[3], aR[0][ks], c2, c3); }
    }
}

__global__ void __launch_bounds__(NT, 1)
corr_hmma_kernel(float* __restrict__ outg)
{
    extern __shared__ char smc[];
    const uint32_t sb = smem_u32(smc);
    const int tid = threadIdx.x, warp = tid >> 5, lane = tid & 31;
    const int m = warp >> 1;
    const int nh = warp & 1;
    const int jb = blockIdx.x, oh = blockIdx.y, b = blockIdx.z;
    const int j0 = jb * 14;
    const int cnt = (jb == 2) ? 13 : 14;   // rows used: R0 .. R0+cnt
    const int R0 = 2 * oh + j0 - MD;

    // ---- prolog fills: A slabs + B rows R0, R0+1 (one group) ----
    const __half* x1b = x1t_g + ((size_t)(b * HH + 2 * oh)) * WW * CHAN;
    fill_slab(sb + SA0, x1b, true, tid);
    fill_slab(sb + SA1, x1b + WW * CHAN, true, tid);
    const __half* x2bb = x2t_g + (size_t)b * HH * WW * CHAN;
#pragma unroll
    for (int k = 0; k < 2; ++k) {
        int row = R0 + k;
        bool v = (unsigned)row < HH;
        fill_slab(sb + SB + k * SLAB, x2bb + (size_t)(v ? row : 0) * WW * CHAN, v, tid);
    }
    asm volatile("cp.async.commit_group;" ::: "memory");

    // ---- ldmatrix addressing ----
    const int cs = min(max(16 * m - 24, 0), 32);
    const int ra = m * 16 + (lane & 15);
    const uint32_t aoff = (uint32_t)(ra * 256);
    const int swa = ra & 7;
    const int ahi = lane >> 4;
    int rb0 = cs + (nh * 4 + 0 + (lane >> 4)) * 8 + (lane & 7);
    int rb1 = cs + (nh * 4 + 2 + (lane >> 4)) * 8 + (lane & 7);
    const uint32_t boff0 = (uint32_t)(rb0 * 256);
    const uint32_t boff1 = (uint32_t)(rb1 * 256);
    const int swb0 = rb0 & 7, swb1 = rb1 & 7;
    const int bhi = (lane >> 3) & 1;

    // ---- epilogue closed-form precompute (permuted Cbuf) ----
    const int owg = tid % 48;
    const int i0g = tid / 48;
    const int m2  = owg >> 3;
    const int cs2 = min(max(16 * m2 - 24, 0), 32);
    const int r0g = (2 * owg) & 15;
    const int c2b = 2 * owg + i0g - MD;
    const int par = c2b & 1;
    const int base0 = m2 * (CBPL / 4) + r0g * CBST;
    const int base1 = base0 + CBST;
    const size_t ob = ((size_t)b * (KD * KD) + (size_t)i0g * KD) * (OHH * OWW)
                      + (size_t)oh * OWW + owg;

    // zero pad slot (col 32 of every plane-row, both buffers)
    {
        int plane = tid >> 5, rem = tid & 31;
        float* P = reinterpret_cast<float*>(smc + SCB + plane * CBPL);
        if (rem < 16) P[rem * CBST + 32] = 0.f;
        else P[(rem - 16) * CBST + 66] = 0.f;
    }

    // ---- hoist A fragments (once per CTA) ----
    asm volatile("cp.async.wait_group 0;" ::: "memory");
    __syncthreads();
    uint32_t aR[2][8][4];
#pragma unroll
    for (int h = 0; h < 2; ++h) {
        const uint32_t ab = sb + (h ? SA1 : SA0) + aoff;
#pragma unroll
        for (int ks = 0; ks < 8; ++ks)
            ldsm4(aR[h][ks][0], aR[h][ks][1], aR[h][ks][2], aR[h][ks][3],
                  ab + (((2 * ks + ahi) ^ swa) << 4));
    }

    const int spOffW = m * (CBPL / 4);
    const int gr = lane >> 2, kk = lane & 3;

    float accA[4][4], accB[4][4];
#pragma unroll
    for (int t = 0; t < 4; ++t)
#pragma unroll
        for (int q = 0; q < 4; ++q) { accA[t][q] = 0.f; accB[t][q] = 0.f; }

    auto do_gather = [&](int jg, int buf) {
        const float* CB = reinterpret_cast<const float*>(smc + SCB + buf * CBUF);
        const float* zp = CB + 32;
        float* op = outg + ob + (size_t)jg * (OHH * OWW);
#pragma unroll
        for (int s = 0; s < 6; ++s) {
            if (s == 5 && tid >= 48) break;
            int c2 = c2b + 8 * s;
            int cl0 = c2 - cs2;
            int cl1 = cl0 + 1;
            const float* p0 = ((unsigned)c2 < 96u)
                ? (CB + base0 + (cl0 >> 1) + par * 33) : zp;
            const float* p1 = ((unsigned)(c2 + 1) < 96u)
                ? (CB + base1 + (cl1 >> 1) + (1 - par) * 33) : zp;
            op[(size_t)s * (8 * KD * OHH * OWW)] = (*p0 + *p1) * (1.0f / 512.0f);
        }
    };

    // one pipelined row-iteration; P retires GEMM(l-1), C accumulates GEMM(l).
    // R12 protocol: sync -> prefetch+commit -> gather -> wait(2) -> mma -> spill.
    auto step = [&](int l, float (&P)[4][4], float (&C)[4][4]) {
        __syncthreads();                  // spill(l-1) visible; slot (l+2)%3 free
        if (l + 2 <= cnt) {
            int row = R0 + l + 2;
            bool v = (unsigned)row < HH;
            fill_slab(sb + SB + ((l + 2) % 3) * SLAB,
                      x2bb + (size_t)(v ? row : 0) * WW * CHAN, v, tid);
        }
        asm volatile("cp.async.commit_group;" ::: "memory");

        if (l >= 2) do_gather(j0 + l - 2, (l + 1) & 1);

        // row l ready when <=2 newest groups pending (rows l+1, l+2)
        asm volatile("cp.async.wait_group 2;" ::: "memory");

        const uint32_t bb = sb + SB + (uint32_t)((l % 3) * SLAB);
        if (l == 0)
            mma_row<false, true >(bb, boff0, boff1, swb0, swb1, bhi, aR, P, C);
        else if (l == cnt)
            mma_row<true , false>(bb, boff0, boff1, swb0, swb1, bhi, aR, P, C);
        else
            mma_row<true , true >(bb, boff0, boff1, swb0, swb1, bhi, aR, P, C);

        // spill P = GEMM(j0+l-1) into buffer l&1, then zero P for reuse
        if (l >= 1) {
            float* Cbm = reinterpret_cast<float*>(smc + SCB + (l & 1) * CBUF) + spOffW;
#pragma unroll
            for (int t = 0; t < 4; ++t) {
                int n = nh * 4 + t;
                int slot = n * 4 + kk;
                Cbm[gr * CBST + slot]            = P[t][0];
                Cbm[gr * CBST + slot + 33]       = P[t][1];
                Cbm[(gr + 8) * CBST + slot]      = P[t][2];
                Cbm[(gr + 8) * CBST + slot + 33] = P[t][3];
            }
#pragma unroll
            for (int t = 0; t < 4; ++t)
#pragma unroll
                for (int q = 0; q < 4; ++q) P[t][q] = 0.f;
        }
    };

    // parity ping-pong: no accumulator copies
    for (int l = 0; l <= cnt; l += 2) {
        step(l, accB, accA);              // even l: C = accA
        if (l + 1 <= cnt) step(l + 1, accA, accB);   // odd l: C = accB
    }
    __syncthreads();
    do_gather(j0 + cnt - 1, cnt & 1);
}

extern "C" void kernel_launch(void* const* d_in, const int* in_sizes, int n_in,
                              void* d_out, int out_size)
{
    (void)in_sizes; (void)n_in; (void)out_size;
    const float* x1 = (const float*)d_in[0];
    const float* x2 = (const float*)d_in[1];
    float* out = (float*)d_out;

    static bool attr_set = false;
    if (!attr_set) {
        cudaFuncSetAttribute(corr_hmma_kernel, cudaFuncAttributeMaxDynamicSharedMemorySize,
                             SMEM_MAIN);
        attr_set = true;
    }
    cvt_kernel<<<dim3(HH, BATCH, 2), 256>>>(x1, x2);
    corr_hmma_kernel<<<dim3(3, OHH, BATCH), NT, SMEM_MAIN>>>(out);
}

// round 15
// speedup vs baseline: 1.1087x; 1.0046x over previous
#include <cuda_runtime.h>
#include <cuda_fp16.h>
#include <cstdint>
#include <cstddef>

#define BATCH 4
#define CHAN  128
#define HH    96
#define WW    96
#define MD    20
#define KD    41
#define OHH   48
#define OWW   48

// fp16 channel-last staging: x[b][h][w][ch]
__device__ __half x1t_g[BATCH * HH * WW * CHAN];
__device__ __half x2t_g[BATCH * HH * WW * CHAN];

// ---------- prepass: fp32 [b][ch][h][w] -> fp16 [b][h][w][ch] ----------
__global__ void __launch_bounds__(256, 4)
cvt_kernel(const float* __restrict__ x1, const float* __restrict__ x2)
{
    __shared__ __half2 hsm[WW * 65];
    const int h = blockIdx.x, b = blockIdx.y;
    const float* src = (blockIdx.z == 0) ? x1 : x2;
    __half* dst = (blockIdx.z == 0) ? x1t_g : x2t_g;
    const float* sp = src + ((size_t)b * CHAN) * (HH * WW) + (size_t)h * WW;

    const int cp0 = threadIdx.x >> 3;
    const int wq8 = threadIdx.x & 7;
#pragma unroll
    for (int cph = 0; cph < 2; ++cph) {
        int cp = cp0 + 32 * cph;
        const float* r0 = sp + (size_t)(2 * cp) * (HH * WW);
        const float* r1 = r0 + HH * WW;
#pragma unroll
        for (int it = 0; it < 3; ++it) {
            int wq = wq8 + 8 * it;
            float4 a = *reinterpret_cast<const float4*>(r0 + 4 * wq);
            float4 c = *reinterpret_cast<const float4*>(r1 + 4 * wq);
            hsm[(4 * wq + 0) * 65 + cp] = __floats2half2_rn(a.x, c.x);
            hsm[(4 * wq + 1) * 65 + cp] = __floats2half2_rn(a.y, c.y);
            hsm[(4 * wq + 2) * 65 + cp] = __floats2half2_rn(a.z, c.z);
            hsm[(4 * wq + 3) * 65 + cp] = __floats2half2_rn(a.w, c.w);
        }
    }
    __syncthreads();
    __half2* dp = reinterpret_cast<__half2*>(dst + ((size_t)(b * HH + h)) * WW * CHAN);
    for (int idx = threadIdx.x; idx < WW * (CHAN / 2); idx += 256) {
        int w = idx >> 6, cp = idx & 63;
        dp[w * (CHAN / 2) + cp] = hsm[w * 65 + cp];
    }
}

// ---------- main kernel: 192-thread CTA = half band (m-blocks 3mh..3mh+2) ----------
#define NT     192
#define ASLAB  12288                     // 48 rows x 256B
#define BSLAB  18432                     // 72 rows x 256B
#define SA0    0
#define SA1    ASLAB
#define SB     (2 * ASLAB)               // 3-slot B ring (72-row slabs)
#define SCB    (SB + 3 * BSLAB)          // 79872
#define CBST   68                        // permuted Cbuf row stride (words)
#define CBPL   (16 * CBST * 4)           // 4352 B per plane
#define CBUF   (3 * CBPL)                // 13056 B per C buffer (3 planes)
#define SMEM_MAIN (SCB + 2 * CBUF)       // 105984 B  -> 2 CTAs/SM

__device__ __forceinline__ uint32_t smem_u32(const void* p) {
    uint32_t a;
    asm("{ .reg .u64 t; cvta.to.shared.u64 t, %1; cvt.u32.u64 %0, t; }" : "=r"(a) : "l"(p));
    return a;
}
__device__ __forceinline__ void cpa16(uint32_t dst, const void* src, uint32_t sz) {
    asm volatile("cp.async.ca.shared.global [%0], [%1], 16, %2;"
                 :: "r"(dst), "l"(src), "r"(sz) : "memory");
}
// copy ROWS x 256B slab (ROWS multiple of 12) with per-row xor swizzle
template <int ROWS>
__device__ __forceinline__ void fill_slab(uint32_t dstb, const __half* src,
                                          bool valid, int tid)
{
#pragma unroll
    for (int it = 0; it < ROWS / 12; ++it) {
        int q = tid + it * NT;
        int n = q >> 4, c = q & 15;
        uint32_t dst = dstb + n * 256 + ((c ^ (n & 7)) << 4);
        cpa16(dst, src + n * CHAN + c * 8, valid ? 16u : 0u);
    }
}
__device__ __forceinline__ void ldsm4(uint32_t& r0, uint32_t& r1, uint32_t& r2,
                                      uint32_t& r3, uint32_t a) {
    asm volatile("ldmatrix.sync.aligned.m8n8.x4.shared.b16 {%0,%1,%2,%3}, [%4];"
                 : "=r"(r0), "=r"(r1), "=r"(r2), "=r"(r3) : "r"(a));
}
__device__ __forceinline__ void mma16816(float* c, const uint32_t* a,
                                         uint32_t b0, uint32_t b1) {
    asm volatile("mma.sync.aligned.m16n8k16.row.col.f32.f16.f16.f32 "
                 "{%0,%1,%2,%3},{%4,%5,%6,%7},{%8,%9},{%0,%1,%2,%3};"
                 : "+f"(c[0]), "+f"(c[1]), "+f"(c[2]), "+f"(c[3])
                 : "r"(a[0]), "r"(a[1]), "r"(a[2]), "r"(a[3]), "r"(b0), "r"(b1));
}

template <bool DOP, bool DOC>
__device__ __forceinline__ void mma_row(uint32_t bb, uint32_t boff0, uint32_t boff1,
                                        int swb0, int swb1, int bhi,
                                        const uint32_t aR[2][8][4],
                                        float accP[4][4], float accC[4][4])
{
#pragma unroll
    for (int ks = 0; ks < 8; ++ks) {
        uint32_t b0, b1, b2, b3, c0, c1, c2, c3;
        ldsm4(b0, b1, b2, b3, bb + boff0 + (((2 * ks + bhi) ^ swb0) << 4));
        ldsm4(c0, c1, c2, c3, bb + boff1 + (((2 * ks + bhi) ^ swb1) << 4));
        if (DOP) { mma16816(accP[0], aR[1][ks], b0, b1);
                   mma16816(accP[1], aR[1][ks], b2, b3);
                   mma16816(accP[2], aR[1][ks], c0, c1);
                   mma16816(accP[3], aR[1][ks], c2, c3); }
        if (DOC) { mma16816(accC[0], aR[0][ks], b0, b1);
                   mma16816(accC[1], aR[0][ks], b2, b3);
                   mma16816(accC[2], aR[0][ks], c0, c1);
                   mma16816(accC[3], aR[0][ks], c2, c3); }
    }
}

__global__ void __launch_bounds__(NT, 2)
corr_hmma_kernel(float* __restrict__ outg)
{
    extern __shared__ char smc[];
    const uint32_t sb = smem_u32(smc);
    const int tid = threadIdx.x, warp = tid >> 5, lane = tid & 31;
    const int m_loc = warp >> 1;          // 0..2
    const int nh = warp & 1;
    const int jb = blockIdx.x >> 1;       // 0..2
    const int mh = blockIdx.x & 1;        // 0..1 : band half
    const int oh = blockIdx.y, b = blockIdx.z;
    const int m = 3 * mh + m_loc;
    const int j0 = jb * 14;
    const int cnt = (jb == 2) ? 13 : 14;  // rows used: R0 .. R0+cnt
    const int R0 = 2 * oh + j0 - MD;
    const int bobase = mh ? 24 : 0;       // B slab global col offset (72 cols)

    // ---- prolog fills: A halves + B rows R0, R0+1 ----
    const __half* x1b = x1t_g + ((size_t)(b * HH + 2 * oh)) * WW * CHAN
                        + (size_t)(48 * mh) * CHAN;
    fill_slab<48>(sb + SA0, x1b, true, tid);
    fill_slab<48>(sb + SA1, x1b + WW * CHAN, true, tid);
    const __half* x2bb = x2t_g + (size_t)b * HH * WW * CHAN + (size_t)bobase * CHAN;
#pragma unroll
    for (int k = 0; k < 2; ++k) {
        int row = R0 + k;
        bool v = (unsigned)row < HH;
        fill_slab<72>(sb + SB + k * BSLAB,
                      x2bb + (size_t)(v ? row : 0) * WW * CHAN, v, tid);
    }
    asm volatile("cp.async.commit_group;" ::: "memory");

    // ---- ldmatrix addressing ----
    const int cs = min(max(16 * m - 24, 0), 32);
    const int ra = m_loc * 16 + (lane & 15);
    const uint32_t aoff = (uint32_t)(ra * 256);
    const int swa = ra & 7;
    const int ahi = lane >> 4;
    int rb0 = cs - bobase + (nh * 4 + 0 + (lane >> 4)) * 8 + (lane & 7);
    int rb1 = cs - bobase + (nh * 4 + 2 + (lane >> 4)) * 8 + (lane & 7);
    const uint32_t boff0 = (uint32_t)(rb0 * 256);
    const uint32_t boff1 = (uint32_t)(rb1 * 256);
    const int swb0 = rb0 & 7, swb1 = rb1 & 7;
    const int bhi = (lane >> 3) & 1;

    // ---- epilogue closed-form precompute ----
    const int owg = tid % 24;             // local ow 0..23
    const int i0g = tid / 24;             // 0..7
    const int ow_g = 24 * mh + owg;
    const int m2l = owg >> 3;             // local plane 0..2
    const int cs2 = min(max(16 * (3 * mh + m2l) - 24, 0), 32);
    const int r0g = (2 * owg) & 15;
    const int c2b = 2 * ow_g + i0g - MD;
    const int par = c2b & 1;
    const int base0 = m2l * (CBPL / 4) + r0g * CBST;
    const int base1 = base0 + CBST;
    const size_t ob = ((size_t)b * (KD * KD) + (size_t)i0g * KD) * (OHH * OWW)
                      + (size_t)oh * OWW + ow_g;

    // zero pad slot (col 32 of every plane-row, both buffers): 6 planes x 16 rows
    if (tid < 96) {
        int plane = tid >> 4, row = tid & 15;
        reinterpret_cast<float*>(smc + SCB + plane * CBPL)[row * CBST + 32] = 0.f;
    }

    // ---- hoist A fragments (once per CTA) ----
    asm volatile("cp.async.wait_group 0;" ::: "memory");
    __syncthreads();
    uint32_t aR[2][8][4];
#pragma unroll
    for (int h = 0; h < 2; ++h) {
        const uint32_t ab = sb + (h ? SA1 : SA0) + aoff;
#pragma unroll
        for (int ks = 0; ks < 8; ++ks)
            ldsm4(aR[h][ks][0], aR[h][ks][1], aR[h][ks][2], aR[h][ks][3],
                  ab + (((2 * ks + ahi) ^ swa) << 4));
    }

    const int spOffW = m_loc * (CBPL / 4);
    const int gr = lane >> 2, kk = lane & 3;

    float accA[4][4], accB[4][4];
#pragma unroll
    for (int t = 0; t < 4; ++t)
#pragma unroll
        for (int q = 0; q < 4; ++q) { accA[t][q] = 0.f; accB[t][q] = 0.f; }

    auto do_gather = [&](int jg, int buf) {
        const float* CB = reinterpret_cast<const float*>(smc + SCB + buf * CBUF);
        const float* zp = CB + 32;
        float* op = outg + ob + (size_t)jg * (OHH * OWW);
#pragma unroll
        for (int s = 0; s < 6; ++s) {
            if (s == 5 && tid >= 24) break;
            int c2 = c2b + 8 * s;
            int cl0 = c2 - cs2;
            int cl1 = cl0 + 1;
            const float* p0 = ((unsigned)c2 < 96u)
                ? (CB + base0 + (cl0 >> 1) + par * 33) : zp;
            const float* p1 = ((unsigned)(c2 + 1) < 96u)
                ? (CB + base1 + (cl1 >> 1) + (1 - par) * 33) : zp;
            op[(size_t)s * (8 * KD * OHH * OWW)] = (*p0 + *p1) * (1.0f / 512.0f);
        }
    };

    // R12 protocol: sync -> prefetch+commit -> gather -> wait(2) -> mma -> spill
    auto step = [&](int l, float (&P)[4][4], float (&C)[4][4]) {
        __syncthreads();
        if (l + 2 <= cnt) {
            int row = R0 + l + 2;
            bool v = (unsigned)row < HH;
            fill_slab<72>(sb + SB + ((l + 2) % 3) * BSLAB,
                          x2bb + (size_t)(v ? row : 0) * WW * CHAN, v, tid);
        }
        asm volatile("cp.async.commit_group;" ::: "memory");

        if (l >= 2) do_gather(j0 + l - 2, (l + 1) & 1);

        asm volatile("cp.async.wait_group 2;" ::: "memory");

        const uint32_t bb = sb + SB + (uint32_t)((l % 3) * BSLAB);
        if (l == 0)
            mma_row<false, true >(bb, boff0, boff1, swb0, swb1, bhi, aR, P, C);
        else if (l == cnt)
            mma_row<true , false>(bb, boff0, boff1, swb0, swb1, bhi, aR, P, C);
        else
            mma_row<true , true >(bb, boff0, boff1, swb0, swb1, bhi, aR, P, C);

        if (l >= 1) {
            float* Cbm = reinterpret_cast<float*>(smc + SCB + (l & 1) * CBUF) + spOffW;
#pragma unroll
            for (int t = 0; t < 4; ++t) {
                int n = nh * 4 + t;
                int slot = n * 4 + kk;
                Cbm[gr * CBST + slot]            = P[t][0];
                Cbm[gr * CBST + slot + 33]       = P[t][1];
                Cbm[(gr + 8) * CBST + slot]      = P[t][2];
                Cbm[(gr + 8) * CBST + slot + 33] = P[t][3];
            }
#pragma unroll
            for (int t = 0; t < 4; ++t)
#pragma unroll
                for (int q = 0; q < 4; ++q) P[t][q] = 0.f;
        }
    };

    for (int l = 0; l <= cnt; l += 2) {
        step(l, accB, accA);
        if (l + 1 <= cnt) step(l + 1, accA, accB);
    }
    __syncthreads();
    do_gather(j0 + cnt - 1, cnt & 1);
}

extern "C" void kernel_launch(void* const* d_in, const int* in_sizes, int n_in,
                              void* d_out, int out_size)
{
    (void)in_sizes; (void)n_in; (void)out_size;
    const float* x1 = (const float*)d_in[0];
    const float* x2 = (const float*)d_in[1];
    float* out = (float*)d_out;

    static bool attr_set = false;
    if (!attr_set) {
        cudaFuncSetAttribute(corr_hmma_kernel, cudaFuncAttributeMaxDynamicSharedMemorySize,
                             SMEM_MAIN);
        attr_set = true;
    }
    cvt_kernel<<<dim3(HH, BATCH, 2), 256>>>(x1, x2);
    corr_hmma_kernel<<<dim3(6, OHH, BATCH), NT, SMEM_MAIN>>>(out);
}